// round 6
// baseline (speedup 1.0000x reference)
#include <cuda_runtime.h>
#include <cuda_fp16.h>
#include <cstdint>

// ---------------- scratch ----------------
__device__ __half g_xh[8192L * 768];
__device__ __half g_wth[3L * 768 * 768], g_wtl[3L * 768 * 768];  // W^T: [s][OUT][D] hi/lo
__device__ __half g_qh[8192L * 768];
__device__ __half g_kh[8192L * 768], g_kl[8192L * 768];
__device__ __half g_vth[4L * 768 * 2048], g_vtl[4L * 768 * 2048]; // V^T per batch: [768][2048]
__device__ float g_s[4L * 2048 * 2048];   // scores; later reused for PV split-K partials
__device__ __half g_ph[4L * 2048 * 2048];

// ---------------- helpers ----------------
__device__ __forceinline__ uint32_t smem_u32(const void* p) {
    uint32_t a;
    asm("{ .reg .u64 t; cvta.to.shared.u64 t, %1; cvt.u32.u64 %0, t; }" : "=r"(a) : "l"(p));
    return a;
}
#define LDSM_X4(R, addr) \
    asm volatile("ldmatrix.sync.aligned.m8n8.x4.shared.b16 {%0,%1,%2,%3}, [%4];" \
        : "=r"((R)[0]), "=r"((R)[1]), "=r"((R)[2]), "=r"((R)[3]) : "r"(addr))
#define MMA16816(C, A, B0, B1) \
    asm volatile("mma.sync.aligned.m16n8k16.row.col.f32.f16.f16.f32 " \
        "{%0,%1,%2,%3}, {%4,%5,%6,%7}, {%8,%9}, {%0,%1,%2,%3};" \
        : "+f"((C)[0]), "+f"((C)[1]), "+f"((C)[2]), "+f"((C)[3]) \
        : "r"((A)[0]), "r"((A)[1]), "r"((A)[2]), "r"((A)[3]), "r"(B0), "r"(B1))

// ---------------- tiling: CTA 128(M) x 256(N), warp 64x64, BK=64, 2 stages ----------------
#define TILE_M 128
#define TILE_N 256
#define BK 64
#define STAGES 2
#define OFF_A 0
#define OFF_BH (16 * 1024)
#define OFF_BL (48 * 1024)
#define STAGE_BYTES (80 * 1024)
#define SMEM_TOTAL (STAGES * STAGE_BYTES)   // 160 KB

__device__ __forceinline__ void load_tile_async(
    uint32_t s_base, const __half* __restrict__ g, long row0, int ld, int k0, int rows, int tid)
{
    // rows x 64 halves (128B/row), SW128 swizzle, 16B chunks
    const int chunks = rows * 8;
    for (int i = tid; i < chunks; i += 256) {
        int r = i >> 3, c = i & 7;
        uint32_t sp = s_base + (uint32_t)(r * 128) + ((uint32_t)(c ^ (r & 7)) * 16);
        const void* gp = g + (row0 + r) * (long)ld + k0 + c * 8;
        asm volatile("cp.async.cg.shared.global [%0], [%1], 16;" :: "r"(sp), "l"(gp) : "memory");
    }
}

// c[i<4][j<8][4] accumulators; D[m,n] += A[m,k]*(Bh[n,k]+Bl[n,k]).
__device__ __forceinline__ void gemm_mainloop(
    uint32_t sm, const __half* __restrict__ pA,
    const __half* __restrict__ pBh, const __half* __restrict__ pBl,
    int K, int lda, int ldb, long bm, long bn, int tid, float (&c)[4][8][4])
{
    const int lane = tid & 31, wid = tid >> 5;
    const int wm = wid & 1, wn = wid >> 1;

    const int a_row = (lane & 7) + ((lane >> 3) & 1) * 8;
    const int a_kh  = lane >> 4;
    const int b_row = (lane & 7) + ((lane >> 4) & 1) * 8;
    const int b_kh  = (lane >> 3) & 1;

    const int iters = K / BK;

    // prologue: stage 0
    load_tile_async(sm + OFF_A,  pA,  bm, lda, 0, TILE_M, tid);
    load_tile_async(sm + OFF_BH, pBh, bn, ldb, 0, TILE_N, tid);
    load_tile_async(sm + OFF_BL, pBl, bn, ldb, 0, TILE_N, tid);
    asm volatile("cp.async.commit_group;" ::: "memory");

    for (int it = 0; it < iters; ++it) {
        asm volatile("cp.async.wait_group 0;" ::: "memory");
        __syncthreads();

        if (it + 1 < iters) {
            const uint32_t sq = sm + ((it + 1) & 1) * STAGE_BYTES;
            const int k0 = (it + 1) * BK;
            load_tile_async(sq + OFF_A,  pA,  bm, lda, k0, TILE_M, tid);
            load_tile_async(sq + OFF_BH, pBh, bn, ldb, k0, TILE_N, tid);
            load_tile_async(sq + OFF_BL, pBl, bn, ldb, k0, TILE_N, tid);
        }
        asm volatile("cp.async.commit_group;" ::: "memory");

        const uint32_t sb = sm + (it & 1) * STAGE_BYTES;
#pragma unroll
        for (int ks = 0; ks < 4; ++ks) {
            uint32_t ah[4][4], bb[8][2];
#pragma unroll
            for (int i = 0; i < 4; ++i) {
                int rg = wm * 64 + i * 16 + a_row;
                uint32_t off = (uint32_t)(rg * 128) +
                               ((uint32_t)((2 * ks + a_kh) ^ (rg & 7)) * 16);
                LDSM_X4(ah[i], sb + OFF_A + off);
            }
            // hi plane
#pragma unroll
            for (int j2 = 0; j2 < 4; ++j2) {
                int rg = wn * 64 + j2 * 16 + b_row;
                uint32_t off = (uint32_t)(rg * 128) +
                               ((uint32_t)((2 * ks + b_kh) ^ (rg & 7)) * 16);
                uint32_t t[4];
                LDSM_X4(t, sb + OFF_BH + off);
                bb[2 * j2][0] = t[0]; bb[2 * j2][1] = t[1];
                bb[2 * j2 + 1][0] = t[2]; bb[2 * j2 + 1][1] = t[3];
            }
#pragma unroll
            for (int i = 0; i < 4; ++i)
#pragma unroll
                for (int j = 0; j < 8; ++j)
                    MMA16816(c[i][j], ah[i], bb[j][0], bb[j][1]);
            // lo plane
#pragma unroll
            for (int j2 = 0; j2 < 4; ++j2) {
                int rg = wn * 64 + j2 * 16 + b_row;
                uint32_t off = (uint32_t)(rg * 128) +
                               ((uint32_t)((2 * ks + b_kh) ^ (rg & 7)) * 16);
                uint32_t t[4];
                LDSM_X4(t, sb + OFF_BL + off);
                bb[2 * j2][0] = t[0]; bb[2 * j2][1] = t[1];
                bb[2 * j2 + 1][0] = t[2]; bb[2 * j2 + 1][1] = t[3];
            }
#pragma unroll
            for (int i = 0; i < 4; ++i)
#pragma unroll
                for (int j = 0; j < 8; ++j)
                    MMA16816(c[i][j], ah[i], bb[j][0], bb[j][1]);
        }
    }
}

// ---------------- QKV kernel (merged, z selects output) ----------------
__global__ void __launch_bounds__(256, 1) qkv_gemm(
    const __half* __restrict__ xh,
    const __half* __restrict__ wth, const __half* __restrict__ wtl,
    __half* __restrict__ qh,
    __half* __restrict__ kh, __half* __restrict__ kl,
    __half* __restrict__ vth, __half* __restrict__ vtl)
{
    extern __shared__ __align__(1024) char smem_raw[];
    const uint32_t sm = smem_u32(smem_raw);
    const int tid = threadIdx.x;
    const int lane = tid & 31, wid = tid >> 5;
    const int wm = wid & 1, wn = wid >> 1;
    const long bm = (long)blockIdx.y * TILE_M;
    const long bn = (long)blockIdx.x * TILE_N;
    const int z = blockIdx.z;
    const long WSL = 768L * 768;

    float c[4][8][4];
#pragma unroll
    for (int i = 0; i < 4; i++)
#pragma unroll
        for (int j = 0; j < 8; j++)
#pragma unroll
            for (int e = 0; e < 4; e++) c[i][j][e] = 0.0f;

    gemm_mainloop(sm, xh, wth + z * WSL, wtl + z * WSL, 768, 768, 768, bm, bn, tid, c);

    const int t4 = lane >> 2;
    const int t2 = (lane & 3) * 2;

    if (z < 2) {
        __half* hp = (z == 0) ? qh : kh;
#pragma unroll
        for (int i = 0; i < 4; ++i) {
            const long r0 = bm + wm * 64 + i * 16 + t4;
#pragma unroll
            for (int j = 0; j < 8; ++j) {
                const long col = bn + wn * 64 + j * 8 + t2;
#pragma unroll
                for (int h = 0; h < 2; ++h) {
                    const long r = r0 + 8 * h;
                    const float va = c[i][j][2 * h], vb = c[i][j][2 * h + 1];
                    const __half ha = __float2half(va), hb = __float2half(vb);
                    *reinterpret_cast<__half2*>(hp + r * 768 + col) = __halves2half2(ha, hb);
                    if (z == 1) {
                        __half2 lv = __halves2half2(
                            __float2half(va - __half2float(ha)),
                            __float2half(vb - __half2float(hb)));
                        *reinterpret_cast<__half2*>(kl + r * 768 + col) = lv;
                    }
                }
            }
        }
    } else {
        // V^T: transpose through smem ([256 cols][132 rows] fp32 = 135KB), coalesced out
        float* smemT = reinterpret_cast<float*>(smem_raw);
        __syncthreads();
#pragma unroll
        for (int i = 0; i < 4; ++i) {
            const int rl0 = wm * 64 + i * 16 + t4;
#pragma unroll
            for (int j = 0; j < 8; ++j) {
                const int cl = wn * 64 + j * 8 + t2;
#pragma unroll
                for (int h = 0; h < 2; ++h) {
                    smemT[(cl + 0) * 132 + rl0 + 8 * h] = c[i][j][2 * h + 0];
                    smemT[(cl + 1) * 132 + rl0 + 8 * h] = c[i][j][2 * h + 1];
                }
            }
        }
        __syncthreads();
        const long batch = bm >> 11, mbase = bm & 2047;
        for (int idx = tid; idx < 256 * 32; idx += 256) {
            const int nl = idx >> 5, m4 = (idx & 31) * 4;
            float4 v = *reinterpret_cast<float4*>(&smemT[nl * 132 + m4]);
            const long o = (batch * 768 + bn + nl) * 2048 + mbase + m4;
            __half h0 = __float2half(v.x), h1 = __float2half(v.y);
            __half h2 = __float2half(v.z), h3 = __float2half(v.w);
            *reinterpret_cast<__half2*>(vth + o)     = __halves2half2(h0, h1);
            *reinterpret_cast<__half2*>(vth + o + 2) = __halves2half2(h2, h3);
            __half l0 = __float2half(v.x - __half2float(h0));
            __half l1 = __float2half(v.y - __half2float(h1));
            __half l2 = __float2half(v.z - __half2float(h2));
            __half l3 = __float2half(v.w - __half2float(h3));
            *reinterpret_cast<__half2*>(vtl + o)     = __halves2half2(l0, l1);
            *reinterpret_cast<__half2*>(vtl + o + 2) = __halves2half2(l2, l3);
        }
    }
}

// ---------------- generic fp32-out GEMM (scores, PV with optional split-K) ----------------
template <bool SPLITK>
__global__ void __launch_bounds__(256, 1) gemm_f32out(
    const __half* __restrict__ A,
    const __half* __restrict__ Bh, const __half* __restrict__ Bl,
    int K, int lda, int ldb, long sA, long sB,
    float alpha, float* __restrict__ C, long sC, int ldc, long sCk)
{
    extern __shared__ __align__(1024) char smem_raw[];
    const uint32_t sm = smem_u32(smem_raw);
    const int tid = threadIdx.x;
    const int lane = tid & 31, wid = tid >> 5;
    const int wm = wid & 1, wn = wid >> 1;
    const long bm = (long)blockIdx.y * TILE_M;
    const long bn = (long)blockIdx.x * TILE_N;
    int b = blockIdx.z, kh = 0;
    if (SPLITK) { kh = b & 1; b >>= 1; }

    const __half* pA  = A  + b * sA + (SPLITK ? kh * K : 0);
    const __half* pBh = Bh + b * sB + (SPLITK ? kh * K : 0);
    const __half* pBl = Bl + b * sB + (SPLITK ? kh * K : 0);
    float* base = C + b * sC + (SPLITK ? kh * sCk : 0);

    float c[4][8][4];
#pragma unroll
    for (int i = 0; i < 4; i++)
#pragma unroll
        for (int j = 0; j < 8; j++)
#pragma unroll
            for (int e = 0; e < 4; e++) c[i][j][e] = 0.0f;

    gemm_mainloop(sm, pA, pBh, pBl, K, lda, ldb, bm, bn, tid, c);

    const int t4 = lane >> 2;
    const int t2 = (lane & 3) * 2;
#pragma unroll
    for (int i = 0; i < 4; ++i) {
        const long r0 = bm + wm * 64 + i * 16 + t4;
        const long r1 = r0 + 8;
#pragma unroll
        for (int j = 0; j < 8; ++j) {
            const long col = bn + wn * 64 + j * 8 + t2;
            *reinterpret_cast<float2*>(base + r0 * ldc + col) =
                make_float2(alpha * c[i][j][0], alpha * c[i][j][1]);
            *reinterpret_cast<float2*>(base + r1 * ldc + col) =
                make_float2(alpha * c[i][j][2], alpha * c[i][j][3]);
        }
    }
}

// ---------------- splits / softmax / reduce ----------------
__global__ void split_x_kernel(const float* __restrict__ x, __half* __restrict__ xh, long n)
{
    long i = (long)blockIdx.x * blockDim.x + threadIdx.x;
    if (i < n) xh[i] = __float2half(x[i]);
}

__global__ void wsplit_kernel(const float* __restrict__ w,
                              __half* __restrict__ hi, __half* __restrict__ lo)
{
    long i = (long)blockIdx.x * blockDim.x + threadIdx.x;
    if (i < 3L * 768 * 768) {
        long s = i / (768 * 768), r = i % (768 * 768);
        long o = r / 768, d = r % 768;
        float f = w[s * 768 * 768 + d * 768 + o];
        __half h = __float2half(f);
        hi[i] = h;
        lo[i] = __float2half(f - __half2float(h));
    }
}

__global__ __launch_bounds__(256) void softmax_kernel(
    const float* __restrict__ S, __half* __restrict__ Ph)
{
    const long row = blockIdx.x;
    const float* p = S + row * 2048;
    const int tid = threadIdx.x;

    float local[8];
    float mx = -1e30f;
#pragma unroll
    for (int r = 0; r < 8; r++) { local[r] = p[tid + r * 256]; mx = fmaxf(mx, local[r]); }

    __shared__ float red[32];
#pragma unroll
    for (int o = 16; o; o >>= 1) mx = fmaxf(mx, __shfl_xor_sync(0xffffffffu, mx, o));
    if ((tid & 31) == 0) red[tid >> 5] = mx;
    __syncthreads();
    if (tid < 32) {
        float v = (tid < 8) ? red[tid] : -1e30f;
#pragma unroll
        for (int o = 4; o; o >>= 1) v = fmaxf(v, __shfl_xor_sync(0xffffffffu, v, o));
        red[tid] = v;
    }
    __syncthreads();
    mx = red[0];

    float s = 0.0f;
#pragma unroll
    for (int r = 0; r < 8; r++) { local[r] = __expf(local[r] - mx); s += local[r]; }
    __shared__ float red2[32];
#pragma unroll
    for (int o = 16; o; o >>= 1) s += __shfl_xor_sync(0xffffffffu, s, o);
    if ((tid & 31) == 0) red2[tid >> 5] = s;
    __syncthreads();
    if (tid < 32) {
        float v = (tid < 8) ? red2[tid] : 0.0f;
#pragma unroll
        for (int o = 4; o; o >>= 1) v += __shfl_xor_sync(0xffffffffu, v, o);
        red2[tid] = v;
    }
    __syncthreads();
    const float inv = 1.0f / red2[0];
#pragma unroll
    for (int r = 0; r < 8; r++)
        Ph[row * 2048 + tid + r * 256] = __float2half(local[r] * inv);
}

__global__ void reduce_add_kernel(const float* __restrict__ p, float* __restrict__ out, long n, long stride)
{
    long i = ((long)blockIdx.x * blockDim.x + threadIdx.x) * 4;
    if (i < n) {
        float4 a = *reinterpret_cast<const float4*>(p + i);
        float4 b = *reinterpret_cast<const float4*>(p + stride + i);
        float4 r = make_float4(a.x + b.x, a.y + b.y, a.z + b.z, a.w + b.w);
        *reinterpret_cast<float4*>(out + i) = r;
    }
}

// ---------------- host ----------------
extern "C" void kernel_launch(void* const* d_in, const int* in_sizes, int n_in,
                              void* d_out, int out_size)
{
    const float* x = (const float*)d_in[0];   // [4,2048,768]
    const float* w = (const float*)d_in[1];   // [3,768,768]
    float* out = (float*)d_out;               // [4,2048,768]

    __half *xh, *wth, *wtl, *qh, *kh, *kl, *vth, *vtl, *ph;
    float* s;
    cudaGetSymbolAddress((void**)&xh, g_xh);
    cudaGetSymbolAddress((void**)&wth, g_wth); cudaGetSymbolAddress((void**)&wtl, g_wtl);
    cudaGetSymbolAddress((void**)&qh, g_qh);
    cudaGetSymbolAddress((void**)&kh, g_kh);   cudaGetSymbolAddress((void**)&kl, g_kl);
    cudaGetSymbolAddress((void**)&vth, g_vth); cudaGetSymbolAddress((void**)&vtl, g_vtl);
    cudaGetSymbolAddress((void**)&ph, g_ph);
    cudaGetSymbolAddress((void**)&s, g_s);

    cudaFuncSetAttribute(qkv_gemm, cudaFuncAttributeMaxDynamicSharedMemorySize, SMEM_TOTAL);
    cudaFuncSetAttribute(gemm_f32out<false>, cudaFuncAttributeMaxDynamicSharedMemorySize, SMEM_TOTAL);
    cudaFuncSetAttribute(gemm_f32out<true>,  cudaFuncAttributeMaxDynamicSharedMemorySize, SMEM_TOTAL);

    split_x_kernel<<<(8192L * 768 + 1023) / 1024, 1024>>>(x, xh, 8192L * 768);
    wsplit_kernel<<<(3L * 768 * 768 + 1023) / 1024, 1024>>>(w, wth, wtl);

    // QKV: M=8192, N=768, K=768, z = {Q, K, V}
    qkv_gemm<<<dim3(3, 64, 3), 256, SMEM_TOTAL>>>(xh, wth, wtl, qh, kh, kl, vth, vtl);

    // scores = Q K^T / 8 : per batch M=2048, N=2048, K=768
    gemm_f32out<false><<<dim3(8, 16, 4), 256, SMEM_TOTAL>>>(
        qh, kh, kl, 768, 768, 768, 2048L * 768, 2048L * 768,
        0.125f, s, 2048L * 2048, 2048, 0L);

    // softmax rows -> P hi
    softmax_kernel<<<8192, 256>>>(s, ph);

    // out = P V with split-K=2: per (batch, khalf) M=2048, N=768, K=1024
    // partials land in g_s (scores are dead now): plane kh at s + kh*6291456
    const long SPLIT_STRIDE = 4L * 2048 * 768;
    gemm_f32out<true><<<dim3(3, 16, 8), 256, SMEM_TOTAL>>>(
        ph, vth, vtl, 1024, 2048, 2048, 2048L * 2048, 768L * 2048,
        1.0f, s, 2048L * 768, 768, SPLIT_STRIDE);

    reduce_add_kernel<<<(int)((SPLIT_STRIDE / 4 + 255) / 256), 256>>>(
        s, out, SPLIT_STRIDE, SPLIT_STRIDE);
}

// round 7
// speedup vs baseline: 1.1512x; 1.1512x over previous
#include <cuda_runtime.h>
#include <cuda_fp16.h>
#include <cstdint>

// ---------------- scratch ----------------
__device__ __half g_xh[8192L * 768];
__device__ __half g_wth[3L * 768 * 768], g_wtl[3L * 768 * 768];  // W^T: [s][OUT][D] hi/lo
__device__ __half g_qh[8192L * 768];
__device__ __half g_kh[8192L * 768], g_kl[8192L * 768];
__device__ __half g_vth[4L * 768 * 2048], g_vtl[4L * 768 * 2048]; // V^T per batch: [768][2048]
__device__ float g_s[4L * 2048 * 2048];   // scores; reused for PV split-K partials
__device__ __half g_ph[4L * 2048 * 2048];

// ---------------- helpers ----------------
__device__ __forceinline__ uint32_t smem_u32(const void* p) {
    uint32_t a;
    asm("{ .reg .u64 t; cvta.to.shared.u64 t, %1; cvt.u32.u64 %0, t; }" : "=r"(a) : "l"(p));
    return a;
}
#define LDSM_X4(R, addr) \
    asm volatile("ldmatrix.sync.aligned.m8n8.x4.shared.b16 {%0,%1,%2,%3}, [%4];" \
        : "=r"((R)[0]), "=r"((R)[1]), "=r"((R)[2]), "=r"((R)[3]) : "r"(addr))
#define MMA16816(C, A, B0, B1) \
    asm volatile("mma.sync.aligned.m16n8k16.row.col.f32.f16.f16.f32 " \
        "{%0,%1,%2,%3}, {%4,%5,%6,%7}, {%8,%9}, {%0,%1,%2,%3};" \
        : "+f"((C)[0]), "+f"((C)[1]), "+f"((C)[2]), "+f"((C)[3]) \
        : "r"((A)[0]), "r"((A)[1]), "r"((A)[2]), "r"((A)[3]), "r"(B0), "r"(B1))

// ---------------- tiling: CTA 128x128, warp grid 4(M)x2(N), warp tile 32x64 ----------------
#define TILE 128
#define BK 64
#define STAGES 2
#define OFF_A 0
#define OFF_BH (16 * 1024)
#define OFF_BL (32 * 1024)
#define STAGE_BYTES (48 * 1024)
#define SMEM_TOTAL (STAGES * STAGE_BYTES)   // 96 KB -> 2 CTAs/SM

__device__ __forceinline__ void load_tile_async(
    uint32_t s_base, const __half* __restrict__ g, long row0, int ld, int k0, int tid)
{
    // 128 rows x 64 halves (128B/row), SW128 swizzle, 16B chunks
#pragma unroll
    for (int rep = 0; rep < 4; ++rep) {
        int i = tid + rep * 256;
        int r = i >> 3, c = i & 7;
        uint32_t sp = s_base + (uint32_t)(r * 128) + ((uint32_t)(c ^ (r & 7)) * 16);
        const void* gp = g + (row0 + r) * (long)ld + k0 + c * 8;
        asm volatile("cp.async.cg.shared.global [%0], [%1], 16;" :: "r"(sp), "l"(gp) : "memory");
    }
}

// c[i<2][j<8][4]; D[m,n] += A[m,k]*(Bh[n,k]+Bl[n,k]), K-major operands.
__device__ __forceinline__ void gemm_mainloop(
    uint32_t sm, const __half* __restrict__ pA,
    const __half* __restrict__ pBh, const __half* __restrict__ pBl,
    int K, int lda, int ldb, long bm, long bn, int tid, float (&c)[2][8][4])
{
    const int lane = tid & 31, wid = tid >> 5;
    const int wm = wid >> 1, wn = wid & 1;

    const int a_row = (lane & 7) + ((lane >> 3) & 1) * 8;
    const int a_kh  = lane >> 4;
    const int b_row = (lane & 7) + ((lane >> 4) & 1) * 8;
    const int b_kh  = (lane >> 3) & 1;

    const int iters = K / BK;

    // prologue: stage 0
    load_tile_async(sm + OFF_A,  pA,  bm, lda, 0, tid);
    load_tile_async(sm + OFF_BH, pBh, bn, ldb, 0, tid);
    load_tile_async(sm + OFF_BL, pBl, bn, ldb, 0, tid);
    asm volatile("cp.async.commit_group;" ::: "memory");

    for (int it = 0; it < iters; ++it) {
        asm volatile("cp.async.wait_group 0;" ::: "memory");
        __syncthreads();

        if (it + 1 < iters) {
            const uint32_t sq = sm + ((it + 1) & 1) * STAGE_BYTES;
            const int k0 = (it + 1) * BK;
            load_tile_async(sq + OFF_A,  pA,  bm, lda, k0, tid);
            load_tile_async(sq + OFF_BH, pBh, bn, ldb, k0, tid);
            load_tile_async(sq + OFF_BL, pBl, bn, ldb, k0, tid);
        }
        asm volatile("cp.async.commit_group;" ::: "memory");

        const uint32_t sb = sm + (it & 1) * STAGE_BYTES;
#pragma unroll
        for (int ks = 0; ks < 4; ++ks) {
            uint32_t ah[2][4], bh[8][2], bl[8][2];
#pragma unroll
            for (int i = 0; i < 2; ++i) {
                int rg = wm * 32 + i * 16 + a_row;
                uint32_t off = (uint32_t)(rg * 128) +
                               ((uint32_t)((2 * ks + a_kh) ^ (rg & 7)) * 16);
                LDSM_X4(ah[i], sb + OFF_A + off);
            }
#pragma unroll
            for (int j2 = 0; j2 < 4; ++j2) {
                int rg = wn * 64 + j2 * 16 + b_row;
                uint32_t off = (uint32_t)(rg * 128) +
                               ((uint32_t)((2 * ks + b_kh) ^ (rg & 7)) * 16);
                uint32_t t[4];
                LDSM_X4(t, sb + OFF_BH + off);
                bh[2 * j2][0] = t[0]; bh[2 * j2][1] = t[1];
                bh[2 * j2 + 1][0] = t[2]; bh[2 * j2 + 1][1] = t[3];
                LDSM_X4(t, sb + OFF_BL + off);
                bl[2 * j2][0] = t[0]; bl[2 * j2][1] = t[1];
                bl[2 * j2 + 1][0] = t[2]; bl[2 * j2 + 1][1] = t[3];
            }
#pragma unroll
            for (int i = 0; i < 2; ++i)
#pragma unroll
                for (int j = 0; j < 8; ++j) {
                    MMA16816(c[i][j], ah[i], bh[j][0], bh[j][1]);
                    MMA16816(c[i][j], ah[i], bl[j][0], bl[j][1]);
                }
        }
    }
}

// ---------------- QKV kernel (merged, z selects output) ----------------
__global__ void __launch_bounds__(256, 2) qkv_gemm(
    const __half* __restrict__ xh,
    const __half* __restrict__ wth, const __half* __restrict__ wtl,
    __half* __restrict__ qh,
    __half* __restrict__ kh, __half* __restrict__ kl,
    __half* __restrict__ vth, __half* __restrict__ vtl)
{
    extern __shared__ __align__(1024) char smem_raw[];
    const uint32_t sm = smem_u32(smem_raw);
    const int tid = threadIdx.x;
    const int lane = tid & 31, wid = tid >> 5;
    const int wm = wid >> 1, wn = wid & 1;
    const long bm = (long)blockIdx.y * TILE;
    const long bn = (long)blockIdx.x * TILE;
    const int z = blockIdx.z;
    const long WSL = 768L * 768;

    float c[2][8][4];
#pragma unroll
    for (int i = 0; i < 2; i++)
#pragma unroll
        for (int j = 0; j < 8; j++)
#pragma unroll
            for (int e = 0; e < 4; e++) c[i][j][e] = 0.0f;

    gemm_mainloop(sm, xh, wth + z * WSL, wtl + z * WSL, 768, 768, 768, bm, bn, tid, c);

    const int t4 = lane >> 2;
    const int t2 = (lane & 3) * 2;

    if (z < 2) {
        __half* hp = (z == 0) ? qh : kh;
#pragma unroll
        for (int i = 0; i < 2; ++i) {
            const long r0 = bm + wm * 32 + i * 16 + t4;
#pragma unroll
            for (int j = 0; j < 8; ++j) {
                const long col = bn + wn * 64 + j * 8 + t2;
#pragma unroll
                for (int h = 0; h < 2; ++h) {
                    const long r = r0 + 8 * h;
                    const float va = c[i][j][2 * h], vb = c[i][j][2 * h + 1];
                    const __half ha = __float2half(va), hb = __float2half(vb);
                    *reinterpret_cast<__half2*>(hp + r * 768 + col) = __halves2half2(ha, hb);
                    if (z == 1) {
                        __half2 lv = __halves2half2(
                            __float2half(va - __half2float(ha)),
                            __float2half(vb - __half2float(hb)));
                        *reinterpret_cast<__half2*>(kl + r * 768 + col) = lv;
                    }
                }
            }
        }
    } else {
        // V^T: transpose via smem ([128 cols][132 rows] fp32 = 67.6KB < 96KB), coalesced out
        float* smemT = reinterpret_cast<float*>(smem_raw);
        __syncthreads();
#pragma unroll
        for (int i = 0; i < 2; ++i) {
            const int rl0 = wm * 32 + i * 16 + t4;
#pragma unroll
            for (int j = 0; j < 8; ++j) {
                const int cl = wn * 64 + j * 8 + t2;
#pragma unroll
                for (int h = 0; h < 2; ++h) {
                    smemT[(cl + 0) * 132 + rl0 + 8 * h] = c[i][j][2 * h + 0];
                    smemT[(cl + 1) * 132 + rl0 + 8 * h] = c[i][j][2 * h + 1];
                }
            }
        }
        __syncthreads();
        const long batch = bm >> 11, mbase = bm & 2047;
#pragma unroll
        for (int rep = 0; rep < 16; ++rep) {
            const int idx = tid + rep * 256;
            const int nl = idx >> 5, m4 = (idx & 31) * 4;
            float4 v = *reinterpret_cast<float4*>(&smemT[nl * 132 + m4]);
            const long o = (batch * 768 + bn + nl) * 2048 + mbase + m4;
            __half h0 = __float2half(v.x), h1 = __float2half(v.y);
            __half h2 = __float2half(v.z), h3 = __float2half(v.w);
            *reinterpret_cast<__half2*>(vth + o)     = __halves2half2(h0, h1);
            *reinterpret_cast<__half2*>(vth + o + 2) = __halves2half2(h2, h3);
            __half l0 = __float2half(v.x - __half2float(h0));
            __half l1 = __float2half(v.y - __half2float(h1));
            __half l2 = __float2half(v.z - __half2float(h2));
            __half l3 = __float2half(v.w - __half2float(h3));
            *reinterpret_cast<__half2*>(vtl + o)     = __halves2half2(l0, l1);
            *reinterpret_cast<__half2*>(vtl + o + 2) = __halves2half2(l2, l3);
        }
    }
}

// ---------------- generic fp32-out GEMM (scores, PV with optional split-K) ----------------
template <bool SPLITK>
__global__ void __launch_bounds__(256, 2) gemm_f32out(
    const __half* __restrict__ A,
    const __half* __restrict__ Bh, const __half* __restrict__ Bl,
    int K, int lda, int ldb, long sA, long sB,
    float alpha, float* __restrict__ C, long sC, int ldc, long sCk)
{
    extern __shared__ __align__(1024) char smem_raw[];
    const uint32_t sm = smem_u32(smem_raw);
    const int tid = threadIdx.x;
    const int lane = tid & 31, wid = tid >> 5;
    const int wm = wid >> 1, wn = wid & 1;
    const long bm = (long)blockIdx.y * TILE;
    const long bn = (long)blockIdx.x * TILE;
    int b = blockIdx.z, kh = 0;
    if (SPLITK) { kh = b & 1; b >>= 1; }

    const __half* pA  = A  + b * sA + (SPLITK ? kh * K : 0);
    const __half* pBh = Bh + b * sB + (SPLITK ? kh * K : 0);
    const __half* pBl = Bl + b * sB + (SPLITK ? kh * K : 0);
    float* base = C + b * sC + (SPLITK ? kh * sCk : 0);

    float c[2][8][4];
#pragma unroll
    for (int i = 0; i < 2; i++)
#pragma unroll
        for (int j = 0; j < 8; j++)
#pragma unroll
            for (int e = 0; e < 4; e++) c[i][j][e] = 0.0f;

    gemm_mainloop(sm, pA, pBh, pBl, K, lda, ldb, bm, bn, tid, c);

    const int t4 = lane >> 2;
    const int t2 = (lane & 3) * 2;
#pragma unroll
    for (int i = 0; i < 2; ++i) {
        const long r0 = bm + wm * 32 + i * 16 + t4;
        const long r1 = r0 + 8;
#pragma unroll
        for (int j = 0; j < 8; ++j) {
            const long col = bn + wn * 64 + j * 8 + t2;
            *reinterpret_cast<float2*>(base + r0 * ldc + col) =
                make_float2(alpha * c[i][j][0], alpha * c[i][j][1]);
            *reinterpret_cast<float2*>(base + r1 * ldc + col) =
                make_float2(alpha * c[i][j][2], alpha * c[i][j][3]);
        }
    }
}

// ---------------- splits / softmax / reduce ----------------
__global__ void split_x_kernel(const float* __restrict__ x, __half* __restrict__ xh, long n)
{
    long i = (long)blockIdx.x * blockDim.x + threadIdx.x;
    if (i < n) xh[i] = __float2half(x[i]);
}

__global__ void wsplit_kernel(const float* __restrict__ w,
                              __half* __restrict__ hi, __half* __restrict__ lo)
{
    long i = (long)blockIdx.x * blockDim.x + threadIdx.x;
    if (i < 3L * 768 * 768) {
        long s = i / (768 * 768), r = i % (768 * 768);
        long o = r / 768, d = r % 768;
        float f = w[s * 768 * 768 + d * 768 + o];
        __half h = __float2half(f);
        hi[i] = h;
        lo[i] = __float2half(f - __half2float(h));
    }
}

__global__ __launch_bounds__(256) void softmax_kernel(
    const float* __restrict__ S, __half* __restrict__ Ph)
{
    const long row = blockIdx.x;
    const float* p = S + row * 2048;
    const int tid = threadIdx.x;

    float local[8];
    float mx = -1e30f;
#pragma unroll
    for (int r = 0; r < 8; r++) { local[r] = p[tid + r * 256]; mx = fmaxf(mx, local[r]); }

    __shared__ float red[32];
#pragma unroll
    for (int o = 16; o; o >>= 1) mx = fmaxf(mx, __shfl_xor_sync(0xffffffffu, mx, o));
    if ((tid & 31) == 0) red[tid >> 5] = mx;
    __syncthreads();
    if (tid < 32) {
        float v = (tid < 8) ? red[tid] : -1e30f;
#pragma unroll
        for (int o = 4; o; o >>= 1) v = fmaxf(v, __shfl_xor_sync(0xffffffffu, v, o));
        red[tid] = v;
    }
    __syncthreads();
    mx = red[0];

    float s = 0.0f;
#pragma unroll
    for (int r = 0; r < 8; r++) { local[r] = __expf(local[r] - mx); s += local[r]; }
    __shared__ float red2[32];
#pragma unroll
    for (int o = 16; o; o >>= 1) s += __shfl_xor_sync(0xffffffffu, s, o);
    if ((tid & 31) == 0) red2[tid >> 5] = s;
    __syncthreads();
    if (tid < 32) {
        float v = (tid < 8) ? red2[tid] : 0.0f;
#pragma unroll
        for (int o = 4; o; o >>= 1) v += __shfl_xor_sync(0xffffffffu, v, o);
        red2[tid] = v;
    }
    __syncthreads();
    const float inv = 1.0f / red2[0];
#pragma unroll
    for (int r = 0; r < 8; r++)
        Ph[row * 2048 + tid + r * 256] = __float2half(local[r] * inv);
}

__global__ void reduce_add_kernel(const float* __restrict__ p, float* __restrict__ out, long n, long stride)
{
    long i = ((long)blockIdx.x * blockDim.x + threadIdx.x) * 4;
    if (i < n) {
        float4 a = *reinterpret_cast<const float4*>(p + i);
        float4 b = *reinterpret_cast<const float4*>(p + stride + i);
        *reinterpret_cast<float4*>(out + i) =
            make_float4(a.x + b.x, a.y + b.y, a.z + b.z, a.w + b.w);
    }
}

// ---------------- host ----------------
extern "C" void kernel_launch(void* const* d_in, const int* in_sizes, int n_in,
                              void* d_out, int out_size)
{
    const float* x = (const float*)d_in[0];   // [4,2048,768]
    const float* w = (const float*)d_in[1];   // [3,768,768]
    float* out = (float*)d_out;               // [4,2048,768]

    __half *xh, *wth, *wtl, *qh, *kh, *kl, *vth, *vtl, *ph;
    float* s;
    cudaGetSymbolAddress((void**)&xh, g_xh);
    cudaGetSymbolAddress((void**)&wth, g_wth); cudaGetSymbolAddress((void**)&wtl, g_wtl);
    cudaGetSymbolAddress((void**)&qh, g_qh);
    cudaGetSymbolAddress((void**)&kh, g_kh);   cudaGetSymbolAddress((void**)&kl, g_kl);
    cudaGetSymbolAddress((void**)&vth, g_vth); cudaGetSymbolAddress((void**)&vtl, g_vtl);
    cudaGetSymbolAddress((void**)&ph, g_ph);
    cudaGetSymbolAddress((void**)&s, g_s);

    cudaFuncSetAttribute(qkv_gemm, cudaFuncAttributeMaxDynamicSharedMemorySize, SMEM_TOTAL);
    cudaFuncSetAttribute(gemm_f32out<false>, cudaFuncAttributeMaxDynamicSharedMemorySize, SMEM_TOTAL);
    cudaFuncSetAttribute(gemm_f32out<true>,  cudaFuncAttributeMaxDynamicSharedMemorySize, SMEM_TOTAL);

    split_x_kernel<<<(8192L * 768 + 1023) / 1024, 1024>>>(x, xh, 8192L * 768);
    wsplit_kernel<<<(3L * 768 * 768 + 1023) / 1024, 1024>>>(w, wth, wtl);

    // QKV: M=8192, N=768, K=768, z = {Q, K, V}
    qkv_gemm<<<dim3(6, 64, 3), 256, SMEM_TOTAL>>>(xh, wth, wtl, qh, kh, kl, vth, vtl);

    // scores = Q K^T / 8 : per batch M=2048, N=2048, K=768
    gemm_f32out<false><<<dim3(16, 16, 4), 256, SMEM_TOTAL>>>(
        qh, kh, kl, 768, 768, 768, 2048L * 768, 2048L * 768,
        0.125f, s, 2048L * 2048, 2048, 0L);

    // softmax rows -> P hi
    softmax_kernel<<<8192, 256>>>(s, ph);

    // out = P V with split-K=2: per (batch, khalf) M=2048, N=768, K=1024
    const long SPLIT_STRIDE = 4L * 2048 * 768;
    gemm_f32out<true><<<dim3(6, 16, 8), 256, SMEM_TOTAL>>>(
        ph, vth, vtl, 1024, 2048, 2048, 2048L * 2048, 768L * 2048,
        1.0f, s, 2048L * 768, 768, SPLIT_STRIDE);

    reduce_add_kernel<<<(int)((SPLIT_STRIDE / 4 + 255) / 256), 256>>>(
        s, out, SPLIT_STRIDE, SPLIT_STRIDE);
}

// round 8
// speedup vs baseline: 1.5372x; 1.3353x over previous
#include <cuda_runtime.h>
#include <cuda_fp16.h>
#include <cstdint>

// ---------------- scratch ----------------
__device__ __half g_xh[8192L * 768];
__device__ __half g_wth[3L * 768 * 768], g_wtl[3L * 768 * 768];  // W^T: [s][OUT][D] hi/lo
__device__ __half g_qh[8192L * 768];
__device__ __half g_kh[8192L * 768];
__device__ __half g_vth[4L * 768 * 2048];                        // V^T per batch: [768][2048]
__device__ float g_s[4L * 2048 * 2048];   // scores; reused for PV split-K partials
__device__ __half g_ph[4L * 2048 * 2048];

// ---------------- helpers ----------------
__device__ __forceinline__ uint32_t smem_u32(const void* p) {
    uint32_t a;
    asm("{ .reg .u64 t; cvta.to.shared.u64 t, %1; cvt.u32.u64 %0, t; }" : "=r"(a) : "l"(p));
    return a;
}
#define LDSM_X4(R, addr) \
    asm volatile("ldmatrix.sync.aligned.m8n8.x4.shared.b16 {%0,%1,%2,%3}, [%4];" \
        : "=r"((R)[0]), "=r"((R)[1]), "=r"((R)[2]), "=r"((R)[3]) : "r"(addr))
#define MMA16816(C, A, B0, B1) \
    asm volatile("mma.sync.aligned.m16n8k16.row.col.f32.f16.f16.f32 " \
        "{%0,%1,%2,%3}, {%4,%5,%6,%7}, {%8,%9}, {%0,%1,%2,%3};" \
        : "+f"((C)[0]), "+f"((C)[1]), "+f"((C)[2]), "+f"((C)[3]) \
        : "r"((A)[0]), "r"((A)[1]), "r"((A)[2]), "r"((A)[3]), "r"(B0), "r"(B1))

// ---------------- tiling: CTA 128x128, warp grid 4(M)x2(N), warp tile 32x64 ----------------
#define TILE 128
#define BK 64
#define OFF_A 0
#define OFF_BH (16 * 1024)
#define OFF_BL (32 * 1024)
#define STAGE_DUAL (48 * 1024)
#define STAGE_MONO (32 * 1024)
#define SMEM_DUAL (2 * STAGE_DUAL)   // 96 KB -> 2 CTAs/SM
#define SMEM_MONO (2 * STAGE_MONO)   // 64 KB -> 2 CTAs/SM

__device__ __forceinline__ void load_tile_async(
    uint32_t s_base, const __half* __restrict__ g, long row0, int ld, int k0, int tid)
{
    // 128 rows x 64 halves (128B/row), SW128 swizzle, 16B chunks
#pragma unroll
    for (int rep = 0; rep < 4; ++rep) {
        int i = tid + rep * 256;
        int r = i >> 3, c = i & 7;
        uint32_t sp = s_base + (uint32_t)(r * 128) + ((uint32_t)(c ^ (r & 7)) * 16);
        const void* gp = g + (row0 + r) * (long)ld + k0 + c * 8;
        asm volatile("cp.async.cg.shared.global [%0], [%1], 16;" :: "r"(sp), "l"(gp) : "memory");
    }
}

// c[i<2][j<8][4]; D[m,n] += A[m,k]*(Bh[n,k] [+ Bl[n,k] if DUAL]), K-major operands.
template <bool DUAL>
__device__ __forceinline__ void gemm_mainloop(
    uint32_t sm, const __half* __restrict__ pA,
    const __half* __restrict__ pBh, const __half* __restrict__ pBl,
    int K, int lda, int ldb, long bm, long bn, int tid, float (&c)[2][8][4])
{
    const int lane = tid & 31, wid = tid >> 5;
    const int wm = wid >> 1, wn = wid & 1;
    const uint32_t stage_bytes = DUAL ? STAGE_DUAL : STAGE_MONO;

    const int a_row = (lane & 7) + ((lane >> 3) & 1) * 8;
    const int a_kh  = lane >> 4;
    const int b_row = (lane & 7) + ((lane >> 4) & 1) * 8;
    const int b_kh  = (lane >> 3) & 1;

    const int iters = K / BK;

    // prologue: stage 0
    load_tile_async(sm + OFF_A,  pA,  bm, lda, 0, tid);
    load_tile_async(sm + OFF_BH, pBh, bn, ldb, 0, tid);
    if (DUAL) load_tile_async(sm + OFF_BL, pBl, bn, ldb, 0, tid);
    asm volatile("cp.async.commit_group;" ::: "memory");

    for (int it = 0; it < iters; ++it) {
        asm volatile("cp.async.wait_group 0;" ::: "memory");
        __syncthreads();

        if (it + 1 < iters) {
            const uint32_t sq = sm + ((it + 1) & 1) * stage_bytes;
            const int k0 = (it + 1) * BK;
            load_tile_async(sq + OFF_A,  pA,  bm, lda, k0, tid);
            load_tile_async(sq + OFF_BH, pBh, bn, ldb, k0, tid);
            if (DUAL) load_tile_async(sq + OFF_BL, pBl, bn, ldb, k0, tid);
        }
        asm volatile("cp.async.commit_group;" ::: "memory");

        const uint32_t sb = sm + (it & 1) * stage_bytes;
#pragma unroll
        for (int ks = 0; ks < 4; ++ks) {
            uint32_t ah[2][4], bh[8][2], bl[8][2];
#pragma unroll
            for (int i = 0; i < 2; ++i) {
                int rg = wm * 32 + i * 16 + a_row;
                uint32_t off = (uint32_t)(rg * 128) +
                               ((uint32_t)((2 * ks + a_kh) ^ (rg & 7)) * 16);
                LDSM_X4(ah[i], sb + OFF_A + off);
            }
#pragma unroll
            for (int j2 = 0; j2 < 4; ++j2) {
                int rg = wn * 64 + j2 * 16 + b_row;
                uint32_t off = (uint32_t)(rg * 128) +
                               ((uint32_t)((2 * ks + b_kh) ^ (rg & 7)) * 16);
                uint32_t t[4];
                LDSM_X4(t, sb + OFF_BH + off);
                bh[2 * j2][0] = t[0]; bh[2 * j2][1] = t[1];
                bh[2 * j2 + 1][0] = t[2]; bh[2 * j2 + 1][1] = t[3];
                if (DUAL) {
                    LDSM_X4(t, sb + OFF_BL + off);
                    bl[2 * j2][0] = t[0]; bl[2 * j2][1] = t[1];
                    bl[2 * j2 + 1][0] = t[2]; bl[2 * j2 + 1][1] = t[3];
                }
            }
#pragma unroll
            for (int i = 0; i < 2; ++i)
#pragma unroll
                for (int j = 0; j < 8; ++j) {
                    MMA16816(c[i][j], ah[i], bh[j][0], bh[j][1]);
                    if (DUAL) MMA16816(c[i][j], ah[i], bl[j][0], bl[j][1]);
                }
        }
    }
}

// ---------------- QKV kernel (merged, z selects output; W exact hi+lo) ----------------
__global__ void __launch_bounds__(256, 2) qkv_gemm(
    const __half* __restrict__ xh,
    const __half* __restrict__ wth, const __half* __restrict__ wtl,
    __half* __restrict__ qh, __half* __restrict__ kh, __half* __restrict__ vth)
{
    extern __shared__ __align__(1024) char smem_raw[];
    const uint32_t sm = smem_u32(smem_raw);
    const int tid = threadIdx.x;
    const int lane = tid & 31, wid = tid >> 5;
    const int wm = wid >> 1, wn = wid & 1;
    const long bm = (long)blockIdx.y * TILE;
    const long bn = (long)blockIdx.x * TILE;
    const int z = blockIdx.z;
    const long WSL = 768L * 768;

    float c[2][8][4];
#pragma unroll
    for (int i = 0; i < 2; i++)
#pragma unroll
        for (int j = 0; j < 8; j++)
#pragma unroll
            for (int e = 0; e < 4; e++) c[i][j][e] = 0.0f;

    gemm_mainloop<true>(sm, xh, wth + z * WSL, wtl + z * WSL, 768, 768, 768, bm, bn, tid, c);

    const int t4 = lane >> 2;
    const int t2 = (lane & 3) * 2;

    if (z < 2) {
        __half* hp = (z == 0) ? qh : kh;
#pragma unroll
        for (int i = 0; i < 2; ++i) {
            const long r0 = bm + wm * 32 + i * 16 + t4;
#pragma unroll
            for (int j = 0; j < 8; ++j) {
                const long col = bn + wn * 64 + j * 8 + t2;
#pragma unroll
                for (int h = 0; h < 2; ++h) {
                    const long r = r0 + 8 * h;
                    *reinterpret_cast<__half2*>(hp + r * 768 + col) = __halves2half2(
                        __float2half(c[i][j][2 * h]), __float2half(c[i][j][2 * h + 1]));
                }
            }
        }
    } else {
        // V^T: transpose via smem ([128 cols][132 rows] fp32 = 67.6KB < 96KB), coalesced out
        float* smemT = reinterpret_cast<float*>(smem_raw);
        __syncthreads();
#pragma unroll
        for (int i = 0; i < 2; ++i) {
            const int rl0 = wm * 32 + i * 16 + t4;
#pragma unroll
            for (int j = 0; j < 8; ++j) {
                const int cl = wn * 64 + j * 8 + t2;
#pragma unroll
                for (int h = 0; h < 2; ++h) {
                    smemT[(cl + 0) * 132 + rl0 + 8 * h] = c[i][j][2 * h + 0];
                    smemT[(cl + 1) * 132 + rl0 + 8 * h] = c[i][j][2 * h + 1];
                }
            }
        }
        __syncthreads();
        const long batch = bm >> 11, mbase = bm & 2047;
#pragma unroll
        for (int rep = 0; rep < 16; ++rep) {
            const int idx = tid + rep * 256;
            const int nl = idx >> 5, m4 = (idx & 31) * 4;
            float4 v = *reinterpret_cast<float4*>(&smemT[nl * 132 + m4]);
            const long o = (batch * 768 + bn + nl) * 2048 + mbase + m4;
            *reinterpret_cast<__half2*>(vth + o) =
                __halves2half2(__float2half(v.x), __float2half(v.y));
            *reinterpret_cast<__half2*>(vth + o + 2) =
                __halves2half2(__float2half(v.z), __float2half(v.w));
        }
    }
}

// ---------------- fp32-out GEMM, single B plane (scores, PV split-K) ----------------
template <bool SPLITK>
__global__ void __launch_bounds__(256, 2) gemm_f32out(
    const __half* __restrict__ A, const __half* __restrict__ Bh,
    int K, int lda, int ldb, long sA, long sB,
    float alpha, float* __restrict__ C, long sC, int ldc, long sCk)
{
    extern __shared__ __align__(1024) char smem_raw[];
    const uint32_t sm = smem_u32(smem_raw);
    const int tid = threadIdx.x;
    const int lane = tid & 31, wid = tid >> 5;
    const int wm = wid >> 1, wn = wid & 1;
    const long bm = (long)blockIdx.y * TILE;
    const long bn = (long)blockIdx.x * TILE;
    int b = blockIdx.z, kh = 0;
    if (SPLITK) { kh = b & 1; b >>= 1; }

    const __half* pA  = A  + b * sA + (SPLITK ? kh * K : 0);
    const __half* pBh = Bh + b * sB + (SPLITK ? kh * K : 0);
    float* base = C + b * sC + (SPLITK ? kh * sCk : 0);

    float c[2][8][4];
#pragma unroll
    for (int i = 0; i < 2; i++)
#pragma unroll
        for (int j = 0; j < 8; j++)
#pragma unroll
            for (int e = 0; e < 4; e++) c[i][j][e] = 0.0f;

    gemm_mainloop<false>(sm, pA, pBh, nullptr, K, lda, ldb, bm, bn, tid, c);

    const int t4 = lane >> 2;
    const int t2 = (lane & 3) * 2;
#pragma unroll
    for (int i = 0; i < 2; ++i) {
        const long r0 = bm + wm * 32 + i * 16 + t4;
        const long r1 = r0 + 8;
#pragma unroll
        for (int j = 0; j < 8; ++j) {
            const long col = bn + wn * 64 + j * 8 + t2;
            *reinterpret_cast<float2*>(base + r0 * ldc + col) =
                make_float2(alpha * c[i][j][0], alpha * c[i][j][1]);
            *reinterpret_cast<float2*>(base + r1 * ldc + col) =
                make_float2(alpha * c[i][j][2], alpha * c[i][j][3]);
        }
    }
}

// ---------------- splits / softmax / reduce ----------------
__global__ void split_x_kernel(const float* __restrict__ x, __half* __restrict__ xh, long n)
{
    long i = (long)blockIdx.x * blockDim.x + threadIdx.x;
    if (i < n) xh[i] = __float2half(x[i]);
}

__global__ void wsplit_kernel(const float* __restrict__ w,
                              __half* __restrict__ hi, __half* __restrict__ lo)
{
    long i = (long)blockIdx.x * blockDim.x + threadIdx.x;
    if (i < 3L * 768 * 768) {
        long s = i / (768 * 768), r = i % (768 * 768);
        long o = r / 768, d = r % 768;
        float f = w[s * 768 * 768 + d * 768 + o];
        __half h = __float2half(f);
        hi[i] = h;
        lo[i] = __float2half(f - __half2float(h));
    }
}

__global__ __launch_bounds__(256) void softmax_kernel(
    const float* __restrict__ S, __half* __restrict__ Ph)
{
    const long row = blockIdx.x;
    const float* p = S + row * 2048;
    const int tid = threadIdx.x;

    float local[8];
    float mx = -1e30f;
#pragma unroll
    for (int r = 0; r < 8; r++) { local[r] = p[tid + r * 256]; mx = fmaxf(mx, local[r]); }

    __shared__ float red[32];
#pragma unroll
    for (int o = 16; o; o >>= 1) mx = fmaxf(mx, __shfl_xor_sync(0xffffffffu, mx, o));
    if ((tid & 31) == 0) red[tid >> 5] = mx;
    __syncthreads();
    if (tid < 32) {
        float v = (tid < 8) ? red[tid] : -1e30f;
#pragma unroll
        for (int o = 4; o; o >>= 1) v = fmaxf(v, __shfl_xor_sync(0xffffffffu, v, o));
        red[tid] = v;
    }
    __syncthreads();
    mx = red[0];

    float s = 0.0f;
#pragma unroll
    for (int r = 0; r < 8; r++) { local[r] = __expf(local[r] - mx); s += local[r]; }
    __shared__ float red2[32];
#pragma unroll
    for (int o = 16; o; o >>= 1) s += __shfl_xor_sync(0xffffffffu, s, o);
    if ((tid & 31) == 0) red2[tid >> 5] = s;
    __syncthreads();
    if (tid < 32) {
        float v = (tid < 8) ? red2[tid] : 0.0f;
#pragma unroll
        for (int o = 4; o; o >>= 1) v += __shfl_xor_sync(0xffffffffu, v, o);
        red2[tid] = v;
    }
    __syncthreads();
    const float inv = 1.0f / red2[0];
#pragma unroll
    for (int r = 0; r < 8; r++)
        Ph[row * 2048 + tid + r * 256] = __float2half(local[r] * inv);
}

__global__ void reduce_add_kernel(const float* __restrict__ p, float* __restrict__ out, long n, long stride)
{
    long i = ((long)blockIdx.x * blockDim.x + threadIdx.x) * 4;
    if (i < n) {
        float4 a = *reinterpret_cast<const float4*>(p + i);
        float4 b = *reinterpret_cast<const float4*>(p + stride + i);
        *reinterpret_cast<float4*>(out + i) =
            make_float4(a.x + b.x, a.y + b.y, a.z + b.z, a.w + b.w);
    }
}

// ---------------- host ----------------
extern "C" void kernel_launch(void* const* d_in, const int* in_sizes, int n_in,
                              void* d_out, int out_size)
{
    const float* x = (const float*)d_in[0];   // [4,2048,768]
    const float* w = (const float*)d_in[1];   // [3,768,768]
    float* out = (float*)d_out;               // [4,2048,768]

    __half *xh, *wth, *wtl, *qh, *kh, *vth, *ph;
    float* s;
    cudaGetSymbolAddress((void**)&xh, g_xh);
    cudaGetSymbolAddress((void**)&wth, g_wth); cudaGetSymbolAddress((void**)&wtl, g_wtl);
    cudaGetSymbolAddress((void**)&qh, g_qh);
    cudaGetSymbolAddress((void**)&kh, g_kh);
    cudaGetSymbolAddress((void**)&vth, g_vth);
    cudaGetSymbolAddress((void**)&ph, g_ph);
    cudaGetSymbolAddress((void**)&s, g_s);

    cudaFuncSetAttribute(qkv_gemm, cudaFuncAttributeMaxDynamicSharedMemorySize, SMEM_DUAL);
    cudaFuncSetAttribute(gemm_f32out<false>, cudaFuncAttributeMaxDynamicSharedMemorySize, SMEM_MONO);
    cudaFuncSetAttribute(gemm_f32out<true>,  cudaFuncAttributeMaxDynamicSharedMemorySize, SMEM_MONO);

    split_x_kernel<<<(8192L * 768 + 1023) / 1024, 1024>>>(x, xh, 8192L * 768);
    wsplit_kernel<<<(3L * 768 * 768 + 1023) / 1024, 1024>>>(w, wth, wtl);

    // QKV: M=8192, N=768, K=768, z = {Q, K, V}; W kept exact (hi+lo)
    qkv_gemm<<<dim3(6, 64, 3), 256, SMEM_DUAL>>>(xh, wth, wtl, qh, kh, vth);

    // scores = Q K^T / 8 : per batch M=2048, N=2048, K=768 (K hi-only)
    gemm_f32out<false><<<dim3(16, 16, 4), 256, SMEM_MONO>>>(
        qh, kh, 768, 768, 768, 2048L * 768, 2048L * 768,
        0.125f, s, 2048L * 2048, 2048, 0L);

    // softmax rows -> P hi
    softmax_kernel<<<8192, 256>>>(s, ph);

    // out = P V with split-K=2: per (batch, khalf) M=2048, N=768, K=1024 (V hi-only)
    const long SPLIT_STRIDE = 4L * 2048 * 768;
    gemm_f32out<true><<<dim3(6, 16, 8), 256, SMEM_MONO>>>(
        ph, vth, 1024, 2048, 2048, 2048L * 2048, 768L * 2048,
        1.0f, s, 2048L * 768, 768, SPLIT_STRIDE);

    reduce_add_kernel<<<(int)((SPLIT_STRIDE / 4 + 255) / 256), 256>>>(
        s, out, SPLIT_STRIDE, SPLIT_STRIDE);
}

// round 9
// speedup vs baseline: 1.8555x; 1.2071x over previous
#include <cuda_runtime.h>
#include <cuda_fp16.h>
#include <cstdint>

// ---------------- scratch ----------------
__device__ __half g_xh[8192L * 768];
__device__ __half g_wth[3L * 768 * 768];   // W^T: [s][OUT][D] fp16
__device__ __half g_qh[8192L * 768];
__device__ __half g_kh[8192L * 768];
__device__ __half g_vth[4L * 768 * 2048];  // V^T per batch: [768][2048]
__device__ float g_s[4L * 2048 * 2048];    // scores; reused for PV split-K partials
__device__ __half g_ph[4L * 2048 * 2048];

// ---------------- helpers ----------------
__device__ __forceinline__ uint32_t smem_u32(const void* p) {
    uint32_t a;
    asm("{ .reg .u64 t; cvta.to.shared.u64 t, %1; cvt.u32.u64 %0, t; }" : "=r"(a) : "l"(p));
    return a;
}
#define LDSM_X4(R, addr) \
    asm volatile("ldmatrix.sync.aligned.m8n8.x4.shared.b16 {%0,%1,%2,%3}, [%4];" \
        : "=r"((R)[0]), "=r"((R)[1]), "=r"((R)[2]), "=r"((R)[3]) : "r"(addr))
#define MMA16816(C, A, B0, B1) \
    asm volatile("mma.sync.aligned.m16n8k16.row.col.f32.f16.f16.f32 " \
        "{%0,%1,%2,%3}, {%4,%5,%6,%7}, {%8,%9}, {%0,%1,%2,%3};" \
        : "+f"((C)[0]), "+f"((C)[1]), "+f"((C)[2]), "+f"((C)[3]) \
        : "r"((A)[0]), "r"((A)[1]), "r"((A)[2]), "r"((A)[3]), "r"(B0), "r"(B1))

// ---------------- tiling: CTA 128x128, warp grid 4(M)x2(N), warp tile 32x64 ----------------
#define TILE 128
#define BK 64
#define STAGES 3
#define OFF_A 0
#define OFF_B (16 * 1024)
#define STAGE_BYTES (32 * 1024)
#define SMEM_TOTAL (STAGES * STAGE_BYTES)   // 96 KB -> 2 CTAs/SM

__device__ __forceinline__ void load_tile_async(
    uint32_t s_base, const __half* __restrict__ g, long row0, int ld, int k0, int tid)
{
    // 128 rows x 64 halves (128B/row), SW128 swizzle, 16B chunks
#pragma unroll
    for (int rep = 0; rep < 4; ++rep) {
        int i = tid + rep * 256;
        int r = i >> 3, c = i & 7;
        uint32_t sp = s_base + (uint32_t)(r * 128) + ((uint32_t)(c ^ (r & 7)) * 16);
        const void* gp = g + (row0 + r) * (long)ld + k0 + c * 8;
        asm volatile("cp.async.cg.shared.global [%0], [%1], 16;" :: "r"(sp), "l"(gp) : "memory");
    }
}

// c[i<2][j<8][4]; D[m,n] += A[m,k]*B[n,k], K-major operands, 3-stage pipeline.
__device__ __forceinline__ void gemm_mainloop(
    uint32_t sm, const __half* __restrict__ pA, const __half* __restrict__ pB,
    int K, int lda, int ldb, long bm, long bn, int tid, float (&c)[2][8][4])
{
    const int lane = tid & 31, wid = tid >> 5;
    const int wm = wid >> 1, wn = wid & 1;

    const int a_row = (lane & 7) + ((lane >> 3) & 1) * 8;
    const int a_kh  = lane >> 4;
    const int b_row = (lane & 7) + ((lane >> 4) & 1) * 8;
    const int b_kh  = (lane >> 3) & 1;

    const int iters = K / BK;

    // prologue: stages 0, 1
#pragma unroll
    for (int s = 0; s < STAGES - 1; ++s) {
        if (s < iters) {
            const uint32_t sb = sm + s * STAGE_BYTES;
            load_tile_async(sb + OFF_A, pA, bm, lda, s * BK, tid);
            load_tile_async(sb + OFF_B, pB, bn, ldb, s * BK, tid);
        }
        asm volatile("cp.async.commit_group;" ::: "memory");
    }

    int st = 0, ld_st = STAGES - 1;
    for (int it = 0; it < iters; ++it) {
        asm volatile("cp.async.wait_group %0;" :: "n"(STAGES - 2) : "memory");
        __syncthreads();

        {
            const int ld_it = it + STAGES - 1;
            if (ld_it < iters) {
                const uint32_t sq = sm + ld_st * STAGE_BYTES;
                load_tile_async(sq + OFF_A, pA, bm, lda, ld_it * BK, tid);
                load_tile_async(sq + OFF_B, pB, bn, ldb, ld_it * BK, tid);
            }
            asm volatile("cp.async.commit_group;" ::: "memory");
            if (++ld_st == STAGES) ld_st = 0;
        }

        const uint32_t sb = sm + st * STAGE_BYTES;
        if (++st == STAGES) st = 0;
#pragma unroll
        for (int ks = 0; ks < 4; ++ks) {
            uint32_t ah[2][4], bb[8][2];
#pragma unroll
            for (int i = 0; i < 2; ++i) {
                int rg = wm * 32 + i * 16 + a_row;
                uint32_t off = (uint32_t)(rg * 128) +
                               ((uint32_t)((2 * ks + a_kh) ^ (rg & 7)) * 16);
                LDSM_X4(ah[i], sb + OFF_A + off);
            }
#pragma unroll
            for (int j2 = 0; j2 < 4; ++j2) {
                int rg = wn * 64 + j2 * 16 + b_row;
                uint32_t off = (uint32_t)(rg * 128) +
                               ((uint32_t)((2 * ks + b_kh) ^ (rg & 7)) * 16);
                uint32_t t[4];
                LDSM_X4(t, sb + OFF_B + off);
                bb[2 * j2][0] = t[0]; bb[2 * j2][1] = t[1];
                bb[2 * j2 + 1][0] = t[2]; bb[2 * j2 + 1][1] = t[3];
            }
#pragma unroll
            for (int i = 0; i < 2; ++i)
#pragma unroll
                for (int j = 0; j < 8; ++j)
                    MMA16816(c[i][j], ah[i], bb[j][0], bb[j][1]);
        }
    }
}

// ---------------- QKV kernel (merged, z selects output) ----------------
__global__ void __launch_bounds__(256, 2) qkv_gemm(
    const __half* __restrict__ xh, const __half* __restrict__ wth,
    __half* __restrict__ qh, __half* __restrict__ kh, __half* __restrict__ vth)
{
    extern __shared__ __align__(1024) char smem_raw[];
    const uint32_t sm = smem_u32(smem_raw);
    const int tid = threadIdx.x;
    const int lane = tid & 31, wid = tid >> 5;
    const int wm = wid >> 1, wn = wid & 1;
    const long bm = (long)blockIdx.y * TILE;
    const long bn = (long)blockIdx.x * TILE;
    const int z = blockIdx.z;
    const long WSL = 768L * 768;

    float c[2][8][4];
#pragma unroll
    for (int i = 0; i < 2; i++)
#pragma unroll
        for (int j = 0; j < 8; j++)
#pragma unroll
            for (int e = 0; e < 4; e++) c[i][j][e] = 0.0f;

    gemm_mainloop(sm, xh, wth + z * WSL, 768, 768, 768, bm, bn, tid, c);

    const int t4 = lane >> 2;
    const int t2 = (lane & 3) * 2;

    if (z < 2) {
        __half* hp = (z == 0) ? qh : kh;
#pragma unroll
        for (int i = 0; i < 2; ++i) {
            const long r0 = bm + wm * 32 + i * 16 + t4;
#pragma unroll
            for (int j = 0; j < 8; ++j) {
                const long col = bn + wn * 64 + j * 8 + t2;
#pragma unroll
                for (int h = 0; h < 2; ++h) {
                    const long r = r0 + 8 * h;
                    *reinterpret_cast<__half2*>(hp + r * 768 + col) = __halves2half2(
                        __float2half(c[i][j][2 * h]), __float2half(c[i][j][2 * h + 1]));
                }
            }
        }
    } else {
        // V^T: transpose via smem ([128 cols][132 rows] fp32 = 67.6KB < 96KB), coalesced out
        float* smemT = reinterpret_cast<float*>(smem_raw);
        __syncthreads();
#pragma unroll
        for (int i = 0; i < 2; ++i) {
            const int rl0 = wm * 32 + i * 16 + t4;
#pragma unroll
            for (int j = 0; j < 8; ++j) {
                const int cl = wn * 64 + j * 8 + t2;
#pragma unroll
                for (int h = 0; h < 2; ++h) {
                    smemT[(cl + 0) * 132 + rl0 + 8 * h] = c[i][j][2 * h + 0];
                    smemT[(cl + 1) * 132 + rl0 + 8 * h] = c[i][j][2 * h + 1];
                }
            }
        }
        __syncthreads();
        const long batch = bm >> 11, mbase = bm & 2047;
#pragma unroll
        for (int rep = 0; rep < 16; ++rep) {
            const int idx = tid + rep * 256;
            const int nl = idx >> 5, m4 = (idx & 31) * 4;
            float4 v = *reinterpret_cast<float4*>(&smemT[nl * 132 + m4]);
            const long o = (batch * 768 + bn + nl) * 2048 + mbase + m4;
            *reinterpret_cast<__half2*>(vth + o) =
                __halves2half2(__float2half(v.x), __float2half(v.y));
            *reinterpret_cast<__half2*>(vth + o + 2) =
                __halves2half2(__float2half(v.z), __float2half(v.w));
        }
    }
}

// ---------------- fp32-out GEMM (scores, PV split-K) ----------------
template <bool SPLITK>
__global__ void __launch_bounds__(256, 2) gemm_f32out(
    const __half* __restrict__ A, const __half* __restrict__ B,
    int K, int lda, int ldb, long sA, long sB,
    float alpha, float* __restrict__ C, long sC, int ldc, long sCk)
{
    extern __shared__ __align__(1024) char smem_raw[];
    const uint32_t sm = smem_u32(smem_raw);
    const int tid = threadIdx.x;
    const int lane = tid & 31, wid = tid >> 5;
    const int wm = wid >> 1, wn = wid & 1;
    const long bm = (long)blockIdx.y * TILE;
    const long bn = (long)blockIdx.x * TILE;
    int b = blockIdx.z, kh = 0;
    if (SPLITK) { kh = b & 1; b >>= 1; }

    const __half* pA = A + b * sA + (SPLITK ? kh * K : 0);
    const __half* pB = B + b * sB + (SPLITK ? kh * K : 0);
    float* base = C + b * sC + (SPLITK ? kh * sCk : 0);

    float c[2][8][4];
#pragma unroll
    for (int i = 0; i < 2; i++)
#pragma unroll
        for (int j = 0; j < 8; j++)
#pragma unroll
            for (int e = 0; e < 4; e++) c[i][j][e] = 0.0f;

    gemm_mainloop(sm, pA, pB, K, lda, ldb, bm, bn, tid, c);

    const int t4 = lane >> 2;
    const int t2 = (lane & 3) * 2;
#pragma unroll
    for (int i = 0; i < 2; ++i) {
        const long r0 = bm + wm * 32 + i * 16 + t4;
        const long r1 = r0 + 8;
#pragma unroll
        for (int j = 0; j < 8; ++j) {
            const long col = bn + wn * 64 + j * 8 + t2;
            *reinterpret_cast<float2*>(base + r0 * ldc + col) =
                make_float2(alpha * c[i][j][0], alpha * c[i][j][1]);
            *reinterpret_cast<float2*>(base + r1 * ldc + col) =
                make_float2(alpha * c[i][j][2], alpha * c[i][j][3]);
        }
    }
}

// ---------------- splits / softmax / reduce ----------------
__global__ void split_x_kernel(const float* __restrict__ x, __half* __restrict__ xh, long n)
{
    long i = (long)blockIdx.x * blockDim.x + threadIdx.x;
    if (i < n) xh[i] = __float2half(x[i]);
}

__global__ void wsplit_kernel(const float* __restrict__ w, __half* __restrict__ hi)
{
    // out[s][o][d] = w[s][d][o]
    long i = (long)blockIdx.x * blockDim.x + threadIdx.x;
    if (i < 3L * 768 * 768) {
        long s = i / (768 * 768), r = i % (768 * 768);
        long o = r / 768, d = r % 768;
        hi[i] = __float2half(w[s * 768 * 768 + d * 768 + o]);
    }
}

__global__ __launch_bounds__(256) void softmax_kernel(
    const float* __restrict__ S, __half* __restrict__ Ph)
{
    const long row = blockIdx.x;
    const float* p = S + row * 2048;
    const int tid = threadIdx.x;

    float local[8];
    float mx = -1e30f;
#pragma unroll
    for (int r = 0; r < 8; r++) { local[r] = p[tid + r * 256]; mx = fmaxf(mx, local[r]); }

    __shared__ float red[32];
#pragma unroll
    for (int o = 16; o; o >>= 1) mx = fmaxf(mx, __shfl_xor_sync(0xffffffffu, mx, o));
    if ((tid & 31) == 0) red[tid >> 5] = mx;
    __syncthreads();
    if (tid < 32) {
        float v = (tid < 8) ? red[tid] : -1e30f;
#pragma unroll
        for (int o = 4; o; o >>= 1) v = fmaxf(v, __shfl_xor_sync(0xffffffffu, v, o));
        red[tid] = v;
    }
    __syncthreads();
    mx = red[0];

    float s = 0.0f;
#pragma unroll
    for (int r = 0; r < 8; r++) { local[r] = __expf(local[r] - mx); s += local[r]; }
    __shared__ float red2[32];
#pragma unroll
    for (int o = 16; o; o >>= 1) s += __shfl_xor_sync(0xffffffffu, s, o);
    if ((tid & 31) == 0) red2[tid >> 5] = s;
    __syncthreads();
    if (tid < 32) {
        float v = (tid < 8) ? red2[tid] : 0.0f;
#pragma unroll
        for (int o = 4; o; o >>= 1) v += __shfl_xor_sync(0xffffffffu, v, o);
        red2[tid] = v;
    }
    __syncthreads();
    const float inv = 1.0f / red2[0];
#pragma unroll
    for (int r = 0; r < 8; r++)
        Ph[row * 2048 + tid + r * 256] = __float2half(local[r] * inv);
}

__global__ void reduce_add_kernel(const float* __restrict__ p, float* __restrict__ out, long n, long stride)
{
    long i = ((long)blockIdx.x * blockDim.x + threadIdx.x) * 4;
    if (i < n) {
        float4 a = *reinterpret_cast<const float4*>(p + i);
        float4 b = *reinterpret_cast<const float4*>(p + stride + i);
        *reinterpret_cast<float4*>(out + i) =
            make_float4(a.x + b.x, a.y + b.y, a.z + b.z, a.w + b.w);
    }
}

// ---------------- host ----------------
extern "C" void kernel_launch(void* const* d_in, const int* in_sizes, int n_in,
                              void* d_out, int out_size)
{
    const float* x = (const float*)d_in[0];   // [4,2048,768]
    const float* w = (const float*)d_in[1];   // [3,768,768]
    float* out = (float*)d_out;               // [4,2048,768]

    __half *xh, *wth, *qh, *kh, *vth, *ph;
    float* s;
    cudaGetSymbolAddress((void**)&xh, g_xh);
    cudaGetSymbolAddress((void**)&wth, g_wth);
    cudaGetSymbolAddress((void**)&qh, g_qh);
    cudaGetSymbolAddress((void**)&kh, g_kh);
    cudaGetSymbolAddress((void**)&vth, g_vth);
    cudaGetSymbolAddress((void**)&ph, g_ph);
    cudaGetSymbolAddress((void**)&s, g_s);

    cudaFuncSetAttribute(qkv_gemm, cudaFuncAttributeMaxDynamicSharedMemorySize, SMEM_TOTAL);
    cudaFuncSetAttribute(gemm_f32out<false>, cudaFuncAttributeMaxDynamicSharedMemorySize, SMEM_TOTAL);
    cudaFuncSetAttribute(gemm_f32out<true>,  cudaFuncAttributeMaxDynamicSharedMemorySize, SMEM_TOTAL);

    split_x_kernel<<<(8192L * 768 + 1023) / 1024, 1024>>>(x, xh, 8192L * 768);
    wsplit_kernel<<<(3L * 768 * 768 + 1023) / 1024, 1024>>>(w, wth);

    // QKV: M=8192, N=768, K=768, z = {Q, K, V}
    qkv_gemm<<<dim3(6, 64, 3), 256, SMEM_TOTAL>>>(xh, wth, qh, kh, vth);

    // scores = Q K^T / 8 : per batch M=2048, N=2048, K=768
    gemm_f32out<false><<<dim3(16, 16, 4), 256, SMEM_TOTAL>>>(
        qh, kh, 768, 768, 768, 2048L * 768, 2048L * 768,
        0.125f, s, 2048L * 2048, 2048, 0L);

    // softmax rows -> P hi
    softmax_kernel<<<8192, 256>>>(s, ph);

    // out = P V with split-K=2: per (batch, khalf) M=2048, N=768, K=1024
    const long SPLIT_STRIDE = 4L * 2048 * 768;
    gemm_f32out<true><<<dim3(6, 16, 8), 256, SMEM_TOTAL>>>(
        ph, vth, 1024, 2048, 2048, 2048L * 2048, 768L * 2048,
        1.0f, s, 2048L * 768, 768, SPLIT_STRIDE);

    reduce_add_kernel<<<(int)((SPLIT_STRIDE / 4 + 255) / 256), 256>>>(
        s, out, SPLIT_STRIDE, SPLIT_STRIDE);
}

// round 11
// speedup vs baseline: 1.8836x; 1.0151x over previous
#include <cuda_runtime.h>
#include <cuda_fp16.h>
#include <cstdint>

// ---------------- scratch ----------------
__device__ __half g_xh[8192L * 768];
__device__ __half g_wth[3L * 768 * 768];   // W^T: [s][OUT][D] fp16
__device__ __half g_qh[8192L * 768];
__device__ __half g_kh[8192L * 768];
__device__ __half g_vth[4L * 768 * 2048];  // V^T per batch: [768][2048]
__device__ __half g_sp[4L * 2048 * 2048];  // fp16 scores, overwritten in place by P
__device__ float g_part[2L * 4 * 2048 * 768]; // PV split-K partials

// ---------------- helpers ----------------
__device__ __forceinline__ uint32_t smem_u32(const void* p) {
    uint32_t a;
    asm("{ .reg .u64 t; cvta.to.shared.u64 t, %1; cvt.u32.u64 %0, t; }" : "=r"(a) : "l"(p));
    return a;
}
#define LDSM_X4(R, addr) \
    asm volatile("ldmatrix.sync.aligned.m8n8.x4.shared.b16 {%0,%1,%2,%3}, [%4];" \
        : "=r"((R)[0]), "=r"((R)[1]), "=r"((R)[2]), "=r"((R)[3]) : "r"(addr))
#define MMA16816(C, A, B0, B1) \
    asm volatile("mma.sync.aligned.m16n8k16.row.col.f32.f16.f16.f32 " \
        "{%0,%1,%2,%3}, {%4,%5,%6,%7}, {%8,%9}, {%0,%1,%2,%3};" \
        : "+f"((C)[0]), "+f"((C)[1]), "+f"((C)[2]), "+f"((C)[3]) \
        : "r"((A)[0]), "r"((A)[1]), "r"((A)[2]), "r"((A)[3]), "r"(B0), "r"(B1))

// ---------------- tiling: CTA 128x128, warp grid 4(M)x2(N), warp tile 32x64 ----------------
#define TILE 128
#define BK 64
#define STAGES 3
#define OFF_A 0
#define OFF_B (16 * 1024)
#define STAGE_BYTES (32 * 1024)
#define SMEM_TOTAL (STAGES * STAGE_BYTES)   // 96 KB -> 2 CTAs/SM

__device__ __forceinline__ void load_tile_async(
    uint32_t s_base, const __half* __restrict__ g, long row0, int ld, int k0, int tid)
{
#pragma unroll
    for (int rep = 0; rep < 4; ++rep) {
        int i = tid + rep * 256;
        int r = i >> 3, c = i & 7;
        uint32_t sp = s_base + (uint32_t)(r * 128) + ((uint32_t)(c ^ (r & 7)) * 16);
        const void* gp = g + (row0 + r) * (long)ld + k0 + c * 8;
        asm volatile("cp.async.cg.shared.global [%0], [%1], 16;" :: "r"(sp), "l"(gp) : "memory");
    }
}

// c[i<2][j<8][4]; D[m,n] += A[m,k]*B[n,k], K-major operands, 3-stage pipeline.
__device__ __forceinline__ void gemm_mainloop(
    uint32_t sm, const __half* __restrict__ pA, const __half* __restrict__ pB,
    int K, int lda, int ldb, long bm, long bn, int tid, float (&c)[2][8][4])
{
    const int lane = tid & 31, wid = tid >> 5;
    const int wm = wid >> 1, wn = wid & 1;

    const int a_row = (lane & 7) + ((lane >> 3) & 1) * 8;
    const int a_kh  = lane >> 4;
    const int b_row = (lane & 7) + ((lane >> 4) & 1) * 8;
    const int b_kh  = (lane >> 3) & 1;

    const int iters = K / BK;

#pragma unroll
    for (int s = 0; s < STAGES - 1; ++s) {
        if (s < iters) {
            const uint32_t sb = sm + s * STAGE_BYTES;
            load_tile_async(sb + OFF_A, pA, bm, lda, s * BK, tid);
            load_tile_async(sb + OFF_B, pB, bn, ldb, s * BK, tid);
        }
        asm volatile("cp.async.commit_group;" ::: "memory");
    }

    int st = 0, ld_st = STAGES - 1;
    for (int it = 0; it < iters; ++it) {
        asm volatile("cp.async.wait_group %0;" :: "n"(STAGES - 2) : "memory");
        __syncthreads();

        {
            const int ld_it = it + STAGES - 1;
            if (ld_it < iters) {
                const uint32_t sq = sm + ld_st * STAGE_BYTES;
                load_tile_async(sq + OFF_A, pA, bm, lda, ld_it * BK, tid);
                load_tile_async(sq + OFF_B, pB, bn, ldb, ld_it * BK, tid);
            }
            asm volatile("cp.async.commit_group;" ::: "memory");
            if (++ld_st == STAGES) ld_st = 0;
        }

        const uint32_t sb = sm + st * STAGE_BYTES;
        if (++st == STAGES) st = 0;
#pragma unroll
        for (int ks = 0; ks < 4; ++ks) {
            uint32_t ah[2][4], bb[8][2];
#pragma unroll
            for (int i = 0; i < 2; ++i) {
                int rg = wm * 32 + i * 16 + a_row;
                uint32_t off = (uint32_t)(rg * 128) +
                               ((uint32_t)((2 * ks + a_kh) ^ (rg & 7)) * 16);
                LDSM_X4(ah[i], sb + OFF_A + off);
            }
#pragma unroll
            for (int j2 = 0; j2 < 4; ++j2) {
                int rg = wn * 64 + j2 * 16 + b_row;
                uint32_t off = (uint32_t)(rg * 128) +
                               ((uint32_t)((2 * ks + b_kh) ^ (rg & 7)) * 16);
                uint32_t t[4];
                LDSM_X4(t, sb + OFF_B + off);
                bb[2 * j2][0] = t[0]; bb[2 * j2][1] = t[1];
                bb[2 * j2 + 1][0] = t[2]; bb[2 * j2 + 1][1] = t[3];
            }
#pragma unroll
            for (int i = 0; i < 2; ++i)
#pragma unroll
                for (int j = 0; j < 8; ++j)
                    MMA16816(c[i][j], ah[i], bb[j][0], bb[j][1]);
        }
    }
}

// ---------------- QKV kernel (merged, z selects output) ----------------
__global__ void __launch_bounds__(256, 2) qkv_gemm(
    const __half* __restrict__ xh, const __half* __restrict__ wth,
    __half* __restrict__ qh, __half* __restrict__ kh, __half* __restrict__ vth)
{
    extern __shared__ __align__(1024) char smem_raw[];
    const uint32_t sm = smem_u32(smem_raw);
    const int tid = threadIdx.x;
    const int lane = tid & 31, wid = tid >> 5;
    const int wm = wid >> 1, wn = wid & 1;
    const long bm = (long)blockIdx.y * TILE;
    const long bn = (long)blockIdx.x * TILE;
    const int z = blockIdx.z;
    const long WSL = 768L * 768;

    float c[2][8][4];
#pragma unroll
    for (int i = 0; i < 2; i++)
#pragma unroll
        for (int j = 0; j < 8; j++)
#pragma unroll
            for (int e = 0; e < 4; e++) c[i][j][e] = 0.0f;

    gemm_mainloop(sm, xh, wth + z * WSL, 768, 768, 768, bm, bn, tid, c);

    const int t4 = lane >> 2;
    const int t2 = (lane & 3) * 2;

    if (z < 2) {
        __half* hp = (z == 0) ? qh : kh;
#pragma unroll
        for (int i = 0; i < 2; ++i) {
            const long r0 = bm + wm * 32 + i * 16 + t4;
#pragma unroll
            for (int j = 0; j < 8; ++j) {
                const long col = bn + wn * 64 + j * 8 + t2;
#pragma unroll
                for (int h = 0; h < 2; ++h) {
                    const long r = r0 + 8 * h;
                    *reinterpret_cast<__half2*>(hp + r * 768 + col) = __halves2half2(
                        __float2half(c[i][j][2 * h]), __float2half(c[i][j][2 * h + 1]));
                }
            }
        }
    } else {
        // V^T: transpose via smem ([128 cols][132 rows] fp32), coalesced out
        float* smemT = reinterpret_cast<float*>(smem_raw);
        __syncthreads();
#pragma unroll
        for (int i = 0; i < 2; ++i) {
            const int rl0 = wm * 32 + i * 16 + t4;
#pragma unroll
            for (int j = 0; j < 8; ++j) {
                const int cl = wn * 64 + j * 8 + t2;
#pragma unroll
                for (int h = 0; h < 2; ++h) {
                    smemT[(cl + 0) * 132 + rl0 + 8 * h] = c[i][j][2 * h + 0];
                    smemT[(cl + 1) * 132 + rl0 + 8 * h] = c[i][j][2 * h + 1];
                }
            }
        }
        __syncthreads();
        const long batch = bm >> 11, mbase = bm & 2047;
#pragma unroll
        for (int rep = 0; rep < 16; ++rep) {
            const int idx = tid + rep * 256;
            const int nl = idx >> 5, m4 = (idx & 31) * 4;
            float4 v = *reinterpret_cast<float4*>(&smemT[nl * 132 + m4]);
            const long o = (batch * 768 + bn + nl) * 2048 + mbase + m4;
            *reinterpret_cast<__half2*>(vth + o) =
                __halves2half2(__float2half(v.x), __float2half(v.y));
            *reinterpret_cast<__half2*>(vth + o + 2) =
                __halves2half2(__float2half(v.z), __float2half(v.w));
        }
    }
}

// ---------------- GEMM: HALF_OUT=1 -> fp16 C (scores); else fp32 C (PV partials) ----------------
template <bool SPLITK, bool HALF_OUT>
__global__ void __launch_bounds__(256, 2) gemm_out(
    const __half* __restrict__ A, const __half* __restrict__ B,
    int K, int lda, int ldb, long sA, long sB,
    float alpha, float* __restrict__ Cf, __half* __restrict__ Ch,
    long sC, int ldc, long sCk)
{
    extern __shared__ __align__(1024) char smem_raw[];
    const uint32_t sm = smem_u32(smem_raw);
    const int tid = threadIdx.x;
    const int lane = tid & 31, wid = tid >> 5;
    const int wm = wid >> 1, wn = wid & 1;
    const long bm = (long)blockIdx.y * TILE;
    const long bn = (long)blockIdx.x * TILE;
    int b = blockIdx.z, kh = 0;
    if (SPLITK) { kh = b & 1; b >>= 1; }

    const __half* pA = A + b * sA + (SPLITK ? kh * K : 0);
    const __half* pB = B + b * sB + (SPLITK ? kh * K : 0);

    float c[2][8][4];
#pragma unroll
    for (int i = 0; i < 2; i++)
#pragma unroll
        for (int j = 0; j < 8; j++)
#pragma unroll
            for (int e = 0; e < 4; e++) c[i][j][e] = 0.0f;

    gemm_mainloop(sm, pA, pB, K, lda, ldb, bm, bn, tid, c);

    const int t4 = lane >> 2;
    const int t2 = (lane & 3) * 2;
#pragma unroll
    for (int i = 0; i < 2; ++i) {
        const long r0 = bm + wm * 32 + i * 16 + t4;
#pragma unroll
        for (int j = 0; j < 8; ++j) {
            const long col = bn + wn * 64 + j * 8 + t2;
#pragma unroll
            for (int h = 0; h < 2; ++h) {
                const long r = r0 + 8 * h;
                const float va = alpha * c[i][j][2 * h];
                const float vb = alpha * c[i][j][2 * h + 1];
                if (HALF_OUT) {
                    __half* base = Ch + b * sC;
                    *reinterpret_cast<__half2*>(base + r * ldc + col) =
                        __halves2half2(__float2half(va), __float2half(vb));
                } else {
                    float* base = Cf + b * sC + (SPLITK ? kh * sCk : 0);
                    *reinterpret_cast<float2*>(base + r * ldc + col) = make_float2(va, vb);
                }
            }
        }
    }
}

// ---------------- merged split (x -> fp16, W -> W^T fp16) ----------------
__global__ void split_all_kernel(const float* __restrict__ x, const float* __restrict__ w,
                                 __half* __restrict__ xh, __half* __restrict__ wth)
{
    const long N1 = 8192L * 768;
    const long N2 = 3L * 768 * 768;
    long i = (long)blockIdx.x * blockDim.x + threadIdx.x;
    if (i < N1) {
        xh[i] = __float2half(x[i]);
    } else if (i < N1 + N2) {
        long j = i - N1;
        long s = j / (768 * 768), r = j % (768 * 768);
        long o = r / 768, d = r % 768;
        wth[j] = __float2half(w[s * 768 * 768 + d * 768 + o]);
    }
}

// ---------------- in-place softmax over fp16 rows of 2048 ----------------
__global__ __launch_bounds__(256) void softmax_kernel(__half* __restrict__ S)
{
    const long row = blockIdx.x;
    __half* p = S + row * 2048;
    const int tid = threadIdx.x;

    // 8 halves per thread, 16B vectorized
    uint4 raw = reinterpret_cast<const uint4*>(p)[tid];
    __half2 hv[4];
    hv[0] = *reinterpret_cast<__half2*>(&raw.x);
    hv[1] = *reinterpret_cast<__half2*>(&raw.y);
    hv[2] = *reinterpret_cast<__half2*>(&raw.z);
    hv[3] = *reinterpret_cast<__half2*>(&raw.w);

    float local[8];
    float mx = -1e30f;
#pragma unroll
    for (int r = 0; r < 4; r++) {
        float2 f = __half22float2(hv[r]);
        local[2 * r] = f.x; local[2 * r + 1] = f.y;
        mx = fmaxf(mx, fmaxf(f.x, f.y));
    }

    __shared__ float red[32];
#pragma unroll
    for (int o = 16; o; o >>= 1) mx = fmaxf(mx, __shfl_xor_sync(0xffffffffu, mx, o));
    if ((tid & 31) == 0) red[tid >> 5] = mx;
    __syncthreads();
    if (tid < 32) {
        float v = (tid < 8) ? red[tid] : -1e30f;
#pragma unroll
        for (int o = 4; o; o >>= 1) v = fmaxf(v, __shfl_xor_sync(0xffffffffu, v, o));
        red[tid] = v;
    }
    __syncthreads();
    mx = red[0];

    float s = 0.0f;
#pragma unroll
    for (int r = 0; r < 8; r++) { local[r] = __expf(local[r] - mx); s += local[r]; }
    __shared__ float red2[32];
#pragma unroll
    for (int o = 16; o; o >>= 1) s += __shfl_xor_sync(0xffffffffu, s, o);
    if ((tid & 31) == 0) red2[tid >> 5] = s;
    __syncthreads();
    if (tid < 32) {
        float v = (tid < 8) ? red2[tid] : 0.0f;
#pragma unroll
        for (int o = 4; o; o >>= 1) v += __shfl_xor_sync(0xffffffffu, v, o);
        red2[tid] = v;
    }
    __syncthreads();
    const float inv = 1.0f / red2[0];

    uint4 out;
    __half2* ov = reinterpret_cast<__half2*>(&out);
#pragma unroll
    for (int r = 0; r < 4; r++)
        ov[r] = __halves2half2(__float2half(local[2 * r] * inv),
                               __float2half(local[2 * r + 1] * inv));
    reinterpret_cast<uint4*>(p)[tid] = out;
}

__global__ void reduce_add_kernel(const float* __restrict__ p, float* __restrict__ out, long n, long stride)
{
    long i = ((long)blockIdx.x * blockDim.x + threadIdx.x) * 4;
    if (i < n) {
        float4 a = *reinterpret_cast<const float4*>(p + i);
        float4 b = *reinterpret_cast<const float4*>(p + stride + i);
        *reinterpret_cast<float4*>(out + i) =
            make_float4(a.x + b.x, a.y + b.y, a.z + b.z, a.w + b.w);
    }
}

// ---------------- host ----------------
extern "C" void kernel_launch(void* const* d_in, const int* in_sizes, int n_in,
                              void* d_out, int out_size)
{
    const float* x = (const float*)d_in[0];   // [4,2048,768]
    const float* w = (const float*)d_in[1];   // [3,768,768]
    float* out = (float*)d_out;               // [4,2048,768]

    __half *xh, *wth, *qh, *kh, *vth, *sp;
    float* part;
    cudaGetSymbolAddress((void**)&xh, g_xh);
    cudaGetSymbolAddress((void**)&wth, g_wth);
    cudaGetSymbolAddress((void**)&qh, g_qh);
    cudaGetSymbolAddress((void**)&kh, g_kh);
    cudaGetSymbolAddress((void**)&vth, g_vth);
    cudaGetSymbolAddress((void**)&sp, g_sp);
    cudaGetSymbolAddress((void**)&part, g_part);

    cudaFuncSetAttribute(qkv_gemm, cudaFuncAttributeMaxDynamicSharedMemorySize, SMEM_TOTAL);
    cudaFuncSetAttribute(gemm_out<false, true>, cudaFuncAttributeMaxDynamicSharedMemorySize, SMEM_TOTAL);
    cudaFuncSetAttribute(gemm_out<true, false>, cudaFuncAttributeMaxDynamicSharedMemorySize, SMEM_TOTAL);

    const long NSPLIT = 8192L * 768 + 3L * 768 * 768;
    split_all_kernel<<<(int)((NSPLIT + 1023) / 1024), 1024>>>(x, w, xh, wth);

    // QKV: M=8192, N=768, K=768, z = {Q, K, V}
    qkv_gemm<<<dim3(6, 64, 3), 256, SMEM_TOTAL>>>(xh, wth, qh, kh, vth);

    // scores = Q K^T / 8 : per batch M=2048, N=2048, K=768 -> fp16
    gemm_out<false, true><<<dim3(16, 16, 4), 256, SMEM_TOTAL>>>(
        qh, kh, 768, 768, 768, 2048L * 768, 2048L * 768,
        0.125f, nullptr, sp, 2048L * 2048, 2048, 0L);

    // softmax in place (fp16 scores -> fp16 P)
    softmax_kernel<<<8192, 256>>>(sp);

    // out = P V with split-K=2: per (batch, khalf) M=2048, N=768, K=1024
    const long SPLIT_STRIDE = 4L * 2048 * 768;
    gemm_out<true, false><<<dim3(6, 16, 8), 256, SMEM_TOTAL>>>(
        sp, vth, 1024, 2048, 2048, 2048L * 2048, 768L * 2048,
        1.0f, part, nullptr, 2048L * 768, 768, SPLIT_STRIDE);

    reduce_add_kernel<<<(int)((SPLIT_STRIDE / 4 + 255) / 256), 256>>>(
        part, out, SPLIT_STRIDE, SPLIT_STRIDE);
}